// round 12
// baseline (speedup 1.0000x reference)
#include <cuda_runtime.h>
#include <cuda_bf16.h>
#include <cstdint>

#define B_SIZE 8192
#define D_SIZE 1024
#define TM 128
#define TN 128
#define KC 64                      // bf16 elems per K-chunk (128 bytes/row)
#define NCHUNK (D_SIZE / KC)       // 16
#define NSTAGE 3
#define NTILES 2080                // 64*65/2 upper-triangle 128x128 tiles
#define INV_TAU 10.0f

// ---------------- device scratch (no allocations allowed) ----------------
__device__ float g_S[B_SIZE];
__device__ float g_P[B_SIZE];
__device__ int   g_C[B_SIZE];
__device__ int   g_ticket;
__device__ __align__(16) __nv_bfloat16 g_Ebf[B_SIZE * D_SIZE];

// ---------------- smem layout ----------------
#define STAGE_BYTES 32768          // A tile 16KB + B tile 16KB
#define OFF_B 16384
#define SM_MISC (NSTAGE * STAGE_BYTES)
#define SM_LA  (SM_MISC + 0)       // int[128]
#define SM_LB  (SM_MISC + 512)
#define SM_RS  (SM_MISC + 1024)    // float[128]
#define SM_RP  (SM_MISC + 1536)
#define SM_CS  (SM_MISC + 2048)
#define SM_CP  (SM_MISC + 2560)
#define SM_HA  (SM_MISC + 3072)    // int[256] label histogram of A rows
#define SM_HB  (SM_MISC + 4096)    // int[256] label histogram of B rows
#define SMEM_TOTAL (SM_MISC + 5120)

// ---------------- helpers ----------------
__device__ __forceinline__ uint32_t smem_u32(const void* p) {
    uint32_t a;
    asm("{ .reg .u64 t; cvta.to.shared.u64 t, %1; cvt.u32.u64 %0, t; }" : "=r"(a) : "l"(p));
    return a;
}
__device__ __forceinline__ void cp_async16(uint32_t dst, const void* src) {
    asm volatile("cp.async.cg.shared.global [%0], [%1], 16;" :: "r"(dst), "l"(src));
}
__device__ __forceinline__ void cp_commit() { asm volatile("cp.async.commit_group;"); }

__device__ __forceinline__ void ldsm4(uint32_t addr, uint32_t* r) {
    asm volatile("ldmatrix.sync.aligned.m8n8.x4.shared.b16 {%0,%1,%2,%3}, [%4];"
                 : "=r"(r[0]), "=r"(r[1]), "=r"(r[2]), "=r"(r[3]) : "r"(addr));
}
__device__ __forceinline__ void mma16816(float* d, const uint32_t* a,
                                         uint32_t b0, uint32_t b1) {
    asm volatile(
        "mma.sync.aligned.m16n8k16.row.col.f32.bf16.bf16.f32 "
        "{%0,%1,%2,%3}, {%4,%5,%6,%7}, {%8,%9}, {%0,%1,%2,%3};"
        : "+f"(d[0]), "+f"(d[1]), "+f"(d[2]), "+f"(d[3])
        : "r"(a[0]), "r"(a[1]), "r"(a[2]), "r"(a[3]), "r"(b0), "r"(b1));
}

// ---------------- packed f32x2 fast-exp ----------------
__device__ __forceinline__ uint64_t pack2(float x) {
    uint64_t r;
    asm("mov.b64 %0, {%1, %1};" : "=l"(r) : "f"(x));
    return r;
}
// e = exp(x * INV_TAU) for a pair of raw accumulator values.
__device__ __forceinline__ void fexp2(float x0, float x1, float& e0, float& e1) {
    const uint64_t cK    = pack2(14.426950408889634f);  // INV_TAU * log2(e)
    const uint64_t cMag  = pack2(12582912.0f);          // 1.5 * 2^23
    const uint64_t cNeg1 = pack2(-1.0f);
    const uint64_t c5 = pack2(1.3333558e-3f);
    const uint64_t c4 = pack2(9.6181291e-3f);
    const uint64_t c3 = pack2(5.5504109e-2f);
    const uint64_t c2 = pack2(2.4022650e-1f);
    const uint64_t c1 = pack2(6.9314718e-1f);
    const uint64_t cOne = pack2(1.0f);

    uint64_t x2, y2, t2, u2, f2, p2;
    asm("mov.b64 %0, {%1, %2};" : "=l"(x2) : "f"(x0), "f"(x1));
    asm("mul.rn.f32x2 %0, %1, %2;" : "=l"(y2) : "l"(x2), "l"(cK));
    asm("add.rn.f32x2 %0, %1, %2;" : "=l"(t2) : "l"(y2), "l"(cMag));
    asm("fma.rn.f32x2 %0, %1, %2, %3;" : "=l"(u2) : "l"(cMag), "l"(cNeg1), "l"(t2)); // t - MAGIC
    asm("fma.rn.f32x2 %0, %1, %2, %3;" : "=l"(f2) : "l"(u2), "l"(cNeg1), "l"(y2));   // y - (t-MAGIC)
    p2 = c5;
    asm("fma.rn.f32x2 %0, %1, %2, %3;" : "=l"(p2) : "l"(p2), "l"(f2), "l"(c4));
    asm("fma.rn.f32x2 %0, %1, %2, %3;" : "=l"(p2) : "l"(p2), "l"(f2), "l"(c3));
    asm("fma.rn.f32x2 %0, %1, %2, %3;" : "=l"(p2) : "l"(p2), "l"(f2), "l"(c2));
    asm("fma.rn.f32x2 %0, %1, %2, %3;" : "=l"(p2) : "l"(p2), "l"(f2), "l"(c1));
    asm("fma.rn.f32x2 %0, %1, %2, %3;" : "=l"(p2) : "l"(p2), "l"(f2), "l"(cOne));

    uint32_t tl, th, pl, ph;
    asm("mov.b64 {%0, %1}, %2;" : "=r"(tl), "=r"(th) : "l"(t2));
    asm("mov.b64 {%0, %1}, %2;" : "=r"(pl), "=r"(ph) : "l"(p2));
    // (tl - 0x4B400000) << 23 == tl << 23  (low 9 bits of the bias are zero)
    e0 = __int_as_float((int)(pl + (tl << 23)));
    e1 = __int_as_float((int)(ph + (th << 23)));
}

// ---------------- kernels ----------------
__global__ void convert_kernel(const float* __restrict__ E) {
    int idx = blockIdx.x * 256 + threadIdx.x;  // one float4 per thread
    if (idx < B_SIZE) { g_S[idx] = 0.f; g_P[idx] = 0.f; g_C[idx] = 0; }
    if (idx == 0) { g_ticket = 0; }
    float4 v = reinterpret_cast<const float4*>(E)[idx];
    __nv_bfloat162* hp = reinterpret_cast<__nv_bfloat162*>(g_Ebf);
    hp[idx * 2 + 0] = __nv_bfloat162(__float2bfloat16(v.x), __float2bfloat16(v.y));
    hp[idx * 2 + 1] = __nv_bfloat162(__float2bfloat16(v.z), __float2bfloat16(v.w));
}

__device__ __forceinline__ void load_chunk(uint32_t sb, int stage, int m0, int n0,
                                           int chunk, int tid) {
    const char* eb = reinterpret_cast<const char*>(g_Ebf);
    uint32_t sbase = sb + stage * STAGE_BYTES;
    size_t colb = (size_t)chunk * 128;
#pragma unroll
    for (int q = 0; q < 8; q++) {
        int idx = tid + q * 128;        // 0..1023
        int row = idx >> 3;             // 0..127
        int c16 = idx & 7;
        uint32_t sw = row * 128 + ((c16 * 16) ^ ((row & 7) << 4));
        size_t gA = (size_t)(m0 + row) * 2048 + colb + c16 * 16;
        size_t gB = (size_t)(n0 + row) * 2048 + colb + c16 * 16;
        cp_async16(sbase + sw, eb + gA);
        cp_async16(sbase + OFF_B + sw, eb + gB);
    }
}

__global__ void __launch_bounds__(128, 2)
sim_kernel(const long long* __restrict__ labels, float* __restrict__ out) {
    // linear tile index -> (bi, bj), bi <= bj, 64x64 block triangle
    const int l = blockIdx.x;
    int bi = (int)((129.0f - sqrtf(fmaxf(129.0f * 129.0f - 8.0f * (float)l, 0.f))) * 0.5f);
    if (bi > 63) bi = 63;
    while (bi > 0 && 64 * bi - (bi * (bi - 1)) / 2 > l) bi--;
    while (64 * (bi + 1) - ((bi + 1) * bi) / 2 <= l) bi++;
    const int bj = bi + (l - (64 * bi - (bi * (bi - 1)) / 2));

    extern __shared__ char smem[];
    const uint32_t sb = smem_u32(smem);
    const int tid = threadIdx.x;
    const int wid = tid >> 5, lane = tid & 31;
    const int m0 = bi * TM, n0 = bj * TN;
    const bool diagTile = (bi == bj);

    int*   lAs = reinterpret_cast<int*>(smem + SM_LA);
    int*   lBs = reinterpret_cast<int*>(smem + SM_LB);
    float* rS = reinterpret_cast<float*>(smem + SM_RS);
    float* rP = reinterpret_cast<float*>(smem + SM_RP);
    float* cS = reinterpret_cast<float*>(smem + SM_CS);
    float* cP = reinterpret_cast<float*>(smem + SM_CP);
    int*   hA = reinterpret_cast<int*>(smem + SM_HA);
    int*   hB = reinterpret_cast<int*>(smem + SM_HB);

    load_chunk(sb, 0, m0, n0, 0, tid); cp_commit();
    load_chunk(sb, 1, m0, n0, 1, tid); cp_commit();

    if (tid < 128) {
        lAs[tid] = (int)labels[m0 + tid];
        lBs[tid] = (int)labels[n0 + tid];
        rS[tid] = 0.f; rP[tid] = 0.f;
        cS[tid] = 0.f; cP[tid] = 0.f;
        hA[tid] = 0; hA[tid + 128] = 0;
        hB[tid] = 0; hB[tid + 128] = 0;
    }
    __syncthreads();
    if (tid < 128) {
        atomicAdd(&hA[lAs[tid] & 255], 1);
        atomicAdd(&hB[lBs[tid] & 255], 1);
    }

    // 4 warps, 2x2; warp tile = 64 rows x 64 cols
    const int wr = wid >> 1, wc = wid & 1;
    const int qr = lane >> 2, qc = lane & 3;
    const uint32_t xmask = (lane & 7) << 4;
    const uint32_t rsel = lane & 15;
    const uint32_t csel = (lane >> 4) << 4;
    uint32_t a_row[4], b_row[4];
#pragma unroll
    for (int g = 0; g < 4; g++) {
        a_row[g] = (wr * 64 + g * 16 + rsel) * 128;
        b_row[g] = (wc * 64 + g * 16 + rsel) * 128 + OFF_B;
    }

    float acc[4][8][4];
#pragma unroll
    for (int i = 0; i < 4; i++)
#pragma unroll
        for (int j = 0; j < 8; j++)
#pragma unroll
            for (int k = 0; k < 4; k++) acc[i][j][k] = 0.f;

    uint32_t a[2][4][4], b[2][4][4];   // register double buffer

    for (int t = 0; t < NCHUNK; t++) {
        if (t < NCHUNK - 1) asm volatile("cp.async.wait_group 1;" ::: "memory");
        else                asm volatile("cp.async.wait_group 0;" ::: "memory");
        __syncthreads();

        const uint32_t stg = sb + (t - NSTAGE * (t / NSTAGE)) * STAGE_BYTES;

        // preload ks=0 fragments
        {
            const uint32_t co = csel ^ xmask;
#pragma unroll
            for (int g = 0; g < 4; g++) ldsm4(stg + a_row[g] + co, a[0][g]);
#pragma unroll
            for (int g = 0; g < 4; g++) ldsm4(stg + b_row[g] + co, b[0][g]);
        }

        // prefetch chunk t+2 (overlaps with the HMMA work below)
        if (t + 2 < NCHUNK) {
            int ps = t + 2 - NSTAGE * ((t + 2) / NSTAGE);
            load_chunk(sb, ps, m0, n0, t + 2, tid);
            cp_commit();
        }

#pragma unroll
        for (int ks = 0; ks < 4; ks++) {
            const int cur = ks & 1, nxt = cur ^ 1;
            if (ks < 3) {
                const uint32_t co = ((ks + 1) * 32 + csel) ^ xmask;
#pragma unroll
                for (int g = 0; g < 4; g++) ldsm4(stg + a_row[g] + co, a[nxt][g]);
#pragma unroll
                for (int g = 0; g < 4; g++) ldsm4(stg + b_row[g] + co, b[nxt][g]);
            }
#pragma unroll
            for (int i = 0; i < 4; i++)
#pragma unroll
                for (int j = 0; j < 8; j++)
                    mma16816(acc[i][j], a[cur][i],
                             b[cur][j >> 1][j & 1], b[cur][j >> 1][(j & 1) + 2]);
        }
    }

    // ---- fused epilogue (f32x2 exp; counts via histogram; raw-acc pos sums) ----
    int rowl[8], la[8];
#pragma unroll
    for (int i = 0; i < 4; i++)
#pragma unroll
        for (int h = 0; h < 2; h++) {
            int ri = i * 2 + h;
            rowl[ri] = wr * 64 + i * 16 + h * 8 + qr;
            la[ri] = lAs[rowl[ri]];
        }
    float rs[8], rp[8];
#pragma unroll
    for (int ri = 0; ri < 8; ri++) { rs[ri] = 0.f; rp[ri] = 0.f; }

    if (!diagTile) {
        // common path: no diag predicate anywhere
#pragma unroll
        for (int j = 0; j < 8; j++) {
            const int lc0 = wc * 64 + j * 8 + qc * 2;
            const int lc1 = lc0 + 1;
            const int lb0 = lBs[lc0], lb1 = lBs[lc1];
            float cs0 = 0.f, cp0 = 0.f, cs1 = 0.f, cp1 = 0.f;
#pragma unroll
            for (int i = 0; i < 4; i++)
#pragma unroll
                for (int h = 0; h < 2; h++) {
                    const int ri = i * 2 + h;
                    const float x0 = acc[i][j][h * 2], x1 = acc[i][j][h * 2 + 1];
                    float e0, e1;
                    fexp2(x0, x1, e0, e1);
                    rs[ri] += e0; cs0 += e0;
                    rs[ri] += e1; cs1 += e1;
                    const float m0v = (lb0 == la[ri]) ? x0 : 0.f;
                    const float m1v = (lb1 == la[ri]) ? x1 : 0.f;
                    rp[ri] += m0v; cp0 += m0v;
                    rp[ri] += m1v; cp1 += m1v;
                }
            // reduce across qr lanes (stride 4): 8 partials -> 1
#pragma unroll
            for (int o = 4; o <= 16; o <<= 1) {
                cs0 += __shfl_xor_sync(0xFFFFFFFFu, cs0, o);
                cp0 += __shfl_xor_sync(0xFFFFFFFFu, cp0, o);
                cs1 += __shfl_xor_sync(0xFFFFFFFFu, cs1, o);
                cp1 += __shfl_xor_sync(0xFFFFFFFFu, cp1, o);
            }
            if (qr == 0) {
                atomicAdd(&cS[lc0], cs0);
                atomicAdd(&cP[lc0], cp0);
                atomicAdd(&cS[lc1], cs1);
                atomicAdd(&cP[lc1], cp1);
            }
        }
    } else {
        // diagonal tile: predicate out self-pairs; no col stats
#pragma unroll
        for (int j = 0; j < 8; j++) {
            const int lc0 = wc * 64 + j * 8 + qc * 2;
            const int lc1 = lc0 + 1;
            const int lb0 = lBs[lc0], lb1 = lBs[lc1];
#pragma unroll
            for (int i = 0; i < 4; i++)
#pragma unroll
                for (int h = 0; h < 2; h++) {
                    const int ri = i * 2 + h;
                    const float x0 = acc[i][j][h * 2], x1 = acc[i][j][h * 2 + 1];
                    float e0, e1;
                    fexp2(x0, x1, e0, e1);
                    if (rowl[ri] != lc0) {
                        rs[ri] += e0;
                        if (lb0 == la[ri]) rp[ri] += x0;
                    }
                    if (rowl[ri] != lc1) {
                        rs[ri] += e1;
                        if (lb1 == la[ri]) rp[ri] += x1;
                    }
                }
        }
    }
    // reduce row stats across qc lanes (stride 1): 4 partials -> 1
#pragma unroll
    for (int ri = 0; ri < 8; ri++) {
#pragma unroll
        for (int o = 1; o <= 2; o <<= 1) {
            rs[ri] += __shfl_xor_sync(0xFFFFFFFFu, rs[ri], o);
            rp[ri] += __shfl_xor_sync(0xFFFFFFFFu, rp[ri], o);
        }
        if (qc == 0) {
            atomicAdd(&rS[rowl[ri]], rs[ri]);
            atomicAdd(&rP[rowl[ri]], rp[ri]);
        }
    }
    __syncthreads();

    if (tid < 128) {
        atomicAdd(&g_S[m0 + tid], rS[tid]);
        atomicAdd(&g_P[m0 + tid], rP[tid] * INV_TAU);
        atomicAdd(&g_C[m0 + tid], hB[lAs[tid] & 255] - (diagTile ? 1 : 0));
        if (!diagTile) {
            atomicAdd(&g_S[n0 + tid], cS[tid]);
            atomicAdd(&g_P[n0 + tid], cP[tid] * INV_TAU);
            atomicAdd(&g_C[n0 + tid], hA[lBs[tid] & 255]);
        }
    }

    // ---- last CTA to finish performs the final reduction (runs in drain tail) ----
    __shared__ int sLast;
    __threadfence();
    __syncthreads();
    if (tid == 0) sLast = (atomicAdd(&g_ticket, 1) == NTILES - 1) ? 1 : 0;
    __syncthreads();
    if (sLast) {
        float loss = 0.f; int cnt = 0;
#pragma unroll 4
        for (int r = tid; r < B_SIZE; r += 128) {
            const int c = g_C[r];
            if (c > 0) { loss += logf(g_S[r]) - g_P[r] / (float)c; cnt++; }
        }
#pragma unroll
        for (int o = 16; o > 0; o >>= 1) {
            loss += __shfl_down_sync(0xFFFFFFFFu, loss, o);
            cnt  += __shfl_down_sync(0xFFFFFFFFu, cnt, o);
        }
        float* sl = reinterpret_cast<float*>(smem + SM_RS);  // reuse smem
        int*   sc = reinterpret_cast<int*>(smem + SM_CS);
        if (lane == 0) { sl[wid] = loss; sc[wid] = cnt; }
        __syncthreads();
        if (tid == 0) {
            float L = sl[0] + sl[1] + sl[2] + sl[3];
            int   C = sc[0] + sc[1] + sc[2] + sc[3];
            out[0] = L / (float)(C > 0 ? C : 1);
        }
    }
}

// ---------------- launch ----------------
extern "C" void kernel_launch(void* const* d_in, const int* in_sizes, int n_in,
                              void* d_out, int out_size) {
    const float*     E      = (const float*)d_in[0];
    const long long* labels = (const long long*)d_in[1];
    float*           out    = (float*)d_out;

    cudaFuncSetAttribute(sim_kernel, cudaFuncAttributeMaxDynamicSharedMemorySize, SMEM_TOTAL);

    convert_kernel<<<(B_SIZE * D_SIZE / 4) / 256, 256>>>(E);

    sim_kernel<<<NTILES, 128, SMEM_TOTAL>>>(labels, out);
}

// round 13
// speedup vs baseline: 1.3792x; 1.3792x over previous
#include <cuda_runtime.h>
#include <cuda_bf16.h>
#include <cstdint>

#define B_SIZE 8192
#define D_SIZE 1024
#define TM 128
#define TN 128
#define KC 64                      // bf16 elems per K-chunk (128 bytes/row)
#define NCHUNK (D_SIZE / KC)       // 16
#define NSTAGE 3
#define NTILES 2080                // 64*65/2 upper-triangle 128x128 tiles
#define INV_TAU 10.0f

// ---------------- device scratch (no allocations allowed) ----------------
__device__ float g_S[B_SIZE];
__device__ float g_P[B_SIZE];
__device__ int   g_C[B_SIZE];
__device__ float g_pl;
__device__ int   g_pc;
__device__ int   g_ticket;
__device__ __align__(16) __nv_bfloat16 g_Ebf[B_SIZE * D_SIZE];

// ---------------- smem layout ----------------
#define STAGE_BYTES 32768          // A tile 16KB + B tile 16KB
#define OFF_B 16384
#define SM_MISC (NSTAGE * STAGE_BYTES)
#define SM_LA  (SM_MISC + 0)       // int[128]
#define SM_LB  (SM_MISC + 512)
#define SM_RS  (SM_MISC + 1024)    // float[128]
#define SM_RP  (SM_MISC + 1536)
#define SM_CS  (SM_MISC + 2048)
#define SM_CP  (SM_MISC + 2560)
#define SM_HA  (SM_MISC + 3072)    // int[256] label histogram of A rows
#define SM_HB  (SM_MISC + 4096)    // int[256] label histogram of B rows
#define SMEM_TOTAL (SM_MISC + 5120)

// ---------------- helpers ----------------
__device__ __forceinline__ uint32_t smem_u32(const void* p) {
    uint32_t a;
    asm("{ .reg .u64 t; cvta.to.shared.u64 t, %1; cvt.u32.u64 %0, t; }" : "=r"(a) : "l"(p));
    return a;
}
__device__ __forceinline__ void cp_async16(uint32_t dst, const void* src) {
    asm volatile("cp.async.cg.shared.global [%0], [%1], 16;" :: "r"(dst), "l"(src));
}
__device__ __forceinline__ void cp_commit() { asm volatile("cp.async.commit_group;"); }

__device__ __forceinline__ void ldsm4(uint32_t addr, uint32_t* r) {
    asm volatile("ldmatrix.sync.aligned.m8n8.x4.shared.b16 {%0,%1,%2,%3}, [%4];"
                 : "=r"(r[0]), "=r"(r[1]), "=r"(r[2]), "=r"(r[3]) : "r"(addr));
}
__device__ __forceinline__ void mma16816(float* d, const uint32_t* a,
                                         uint32_t b0, uint32_t b1) {
    asm volatile(
        "mma.sync.aligned.m16n8k16.row.col.f32.bf16.bf16.f32 "
        "{%0,%1,%2,%3}, {%4,%5,%6,%7}, {%8,%9}, {%0,%1,%2,%3};"
        : "+f"(d[0]), "+f"(d[1]), "+f"(d[2]), "+f"(d[3])
        : "r"(a[0]), "r"(a[1]), "r"(a[2]), "r"(a[3]), "r"(b0), "r"(b1));
}

// ---------------- packed f32x2 fast-exp ----------------
__device__ __forceinline__ uint64_t pack2(float x) {
    uint64_t r;
    asm("mov.b64 %0, {%1, %1};" : "=l"(r) : "f"(x));
    return r;
}
// e = exp(x * INV_TAU) for a pair of raw accumulator values.
__device__ __forceinline__ void fexp2(float x0, float x1, float& e0, float& e1) {
    const uint64_t cK    = pack2(14.426950408889634f);  // INV_TAU * log2(e)
    const uint64_t cMag  = pack2(12582912.0f);          // 1.5 * 2^23
    const uint64_t cNeg1 = pack2(-1.0f);
    const uint64_t c5 = pack2(1.3333558e-3f);
    const uint64_t c4 = pack2(9.6181291e-3f);
    const uint64_t c3 = pack2(5.5504109e-2f);
    const uint64_t c2 = pack2(2.4022650e-1f);
    const uint64_t c1 = pack2(6.9314718e-1f);
    const uint64_t cOne = pack2(1.0f);

    uint64_t x2, y2, t2, u2, f2, p2;
    asm("mov.b64 %0, {%1, %2};" : "=l"(x2) : "f"(x0), "f"(x1));
    asm("mul.rn.f32x2 %0, %1, %2;" : "=l"(y2) : "l"(x2), "l"(cK));
    asm("add.rn.f32x2 %0, %1, %2;" : "=l"(t2) : "l"(y2), "l"(cMag));
    asm("fma.rn.f32x2 %0, %1, %2, %3;" : "=l"(u2) : "l"(cMag), "l"(cNeg1), "l"(t2)); // t - MAGIC
    asm("fma.rn.f32x2 %0, %1, %2, %3;" : "=l"(f2) : "l"(u2), "l"(cNeg1), "l"(y2));   // y - (t-MAGIC)
    p2 = c5;
    asm("fma.rn.f32x2 %0, %1, %2, %3;" : "=l"(p2) : "l"(p2), "l"(f2), "l"(c4));
    asm("fma.rn.f32x2 %0, %1, %2, %3;" : "=l"(p2) : "l"(p2), "l"(f2), "l"(c3));
    asm("fma.rn.f32x2 %0, %1, %2, %3;" : "=l"(p2) : "l"(p2), "l"(f2), "l"(c2));
    asm("fma.rn.f32x2 %0, %1, %2, %3;" : "=l"(p2) : "l"(p2), "l"(f2), "l"(c1));
    asm("fma.rn.f32x2 %0, %1, %2, %3;" : "=l"(p2) : "l"(p2), "l"(f2), "l"(cOne));

    uint32_t tl, th, pl, ph;
    asm("mov.b64 {%0, %1}, %2;" : "=r"(tl), "=r"(th) : "l"(t2));
    asm("mov.b64 {%0, %1}, %2;" : "=r"(pl), "=r"(ph) : "l"(p2));
    // (tl - 0x4B400000) << 23 == tl << 23  (low 9 bits of the bias are zero)
    e0 = __int_as_float((int)(pl + (tl << 23)));
    e1 = __int_as_float((int)(ph + (th << 23)));
}

// ---------------- kernels ----------------
__global__ void convert_kernel(const float* __restrict__ E) {
    int idx = blockIdx.x * 256 + threadIdx.x;  // one float4 per thread
    if (idx < B_SIZE) { g_S[idx] = 0.f; g_P[idx] = 0.f; g_C[idx] = 0; }
    if (idx == 0) { g_pl = 0.f; g_pc = 0; g_ticket = 0; }
    float4 v = reinterpret_cast<const float4*>(E)[idx];
    __nv_bfloat162* hp = reinterpret_cast<__nv_bfloat162*>(g_Ebf);
    hp[idx * 2 + 0] = __nv_bfloat162(__float2bfloat16(v.x), __float2bfloat16(v.y));
    hp[idx * 2 + 1] = __nv_bfloat162(__float2bfloat16(v.z), __float2bfloat16(v.w));
}

__device__ __forceinline__ void load_chunk(uint32_t sb, int stage, int m0, int n0,
                                           int chunk, int tid) {
    const char* eb = reinterpret_cast<const char*>(g_Ebf);
    uint32_t sbase = sb + stage * STAGE_BYTES;
    size_t colb = (size_t)chunk * 128;
#pragma unroll
    for (int q = 0; q < 8; q++) {
        int idx = tid + q * 128;        // 0..1023
        int row = idx >> 3;             // 0..127
        int c16 = idx & 7;
        uint32_t sw = row * 128 + ((c16 * 16) ^ ((row & 7) << 4));
        size_t gA = (size_t)(m0 + row) * 2048 + colb + c16 * 16;
        size_t gB = (size_t)(n0 + row) * 2048 + colb + c16 * 16;
        cp_async16(sbase + sw, eb + gA);
        cp_async16(sbase + OFF_B + sw, eb + gB);
    }
}

__global__ void __launch_bounds__(128, 2)
sim_kernel(const long long* __restrict__ labels) {
    // linear tile index -> (bi, bj), bi <= bj, 64x64 block triangle
    const int l = blockIdx.x;
    int bi = (int)((129.0f - sqrtf(fmaxf(129.0f * 129.0f - 8.0f * (float)l, 0.f))) * 0.5f);
    if (bi > 63) bi = 63;
    while (bi > 0 && 64 * bi - (bi * (bi - 1)) / 2 > l) bi--;
    while (64 * (bi + 1) - ((bi + 1) * bi) / 2 <= l) bi++;
    const int bj = bi + (l - (64 * bi - (bi * (bi - 1)) / 2));

    extern __shared__ char smem[];
    const uint32_t sb = smem_u32(smem);
    const int tid = threadIdx.x;
    const int wid = tid >> 5, lane = tid & 31;
    const int m0 = bi * TM, n0 = bj * TN;
    const bool diagTile = (bi == bj);

    int*   lAs = reinterpret_cast<int*>(smem + SM_LA);
    int*   lBs = reinterpret_cast<int*>(smem + SM_LB);
    float* rS = reinterpret_cast<float*>(smem + SM_RS);
    float* rP = reinterpret_cast<float*>(smem + SM_RP);
    float* cS = reinterpret_cast<float*>(smem + SM_CS);
    float* cP = reinterpret_cast<float*>(smem + SM_CP);
    int*   hA = reinterpret_cast<int*>(smem + SM_HA);
    int*   hB = reinterpret_cast<int*>(smem + SM_HB);

    load_chunk(sb, 0, m0, n0, 0, tid); cp_commit();
    load_chunk(sb, 1, m0, n0, 1, tid); cp_commit();

    if (tid < 128) {
        lAs[tid] = (int)labels[m0 + tid];
        lBs[tid] = (int)labels[n0 + tid];
        rS[tid] = 0.f; rP[tid] = 0.f;
        cS[tid] = 0.f; cP[tid] = 0.f;
        hA[tid] = 0; hA[tid + 128] = 0;
        hB[tid] = 0; hB[tid + 128] = 0;
    }
    __syncthreads();
    if (tid < 128) {
        atomicAdd(&hA[lAs[tid] & 255], 1);
        atomicAdd(&hB[lBs[tid] & 255], 1);
    }

    // 4 warps, 2x2; warp tile = 64 rows x 64 cols
    const int wr = wid >> 1, wc = wid & 1;
    const int qr = lane >> 2, qc = lane & 3;
    const uint32_t xmask = (lane & 7) << 4;
    const uint32_t rsel = lane & 15;
    const uint32_t csel = (lane >> 4) << 4;
    uint32_t a_row[4], b_row[4];
#pragma unroll
    for (int g = 0; g < 4; g++) {
        a_row[g] = (wr * 64 + g * 16 + rsel) * 128;
        b_row[g] = (wc * 64 + g * 16 + rsel) * 128 + OFF_B;
    }

    float acc[4][8][4];
#pragma unroll
    for (int i = 0; i < 4; i++)
#pragma unroll
        for (int j = 0; j < 8; j++)
#pragma unroll
            for (int k = 0; k < 4; k++) acc[i][j][k] = 0.f;

    uint32_t a[2][4][4], b[2][4][4];   // register double buffer

    for (int t = 0; t < NCHUNK; t++) {
        if (t < NCHUNK - 1) asm volatile("cp.async.wait_group 1;" ::: "memory");
        else                asm volatile("cp.async.wait_group 0;" ::: "memory");
        __syncthreads();

        const uint32_t stg = sb + (t - NSTAGE * (t / NSTAGE)) * STAGE_BYTES;

        // preload ks=0 fragments
        {
            const uint32_t co = csel ^ xmask;
#pragma unroll
            for (int g = 0; g < 4; g++) ldsm4(stg + a_row[g] + co, a[0][g]);
#pragma unroll
            for (int g = 0; g < 4; g++) ldsm4(stg + b_row[g] + co, b[0][g]);
        }

        // prefetch chunk t+2 (overlaps with the HMMA work below)
        if (t + 2 < NCHUNK) {
            int ps = t + 2 - NSTAGE * ((t + 2) / NSTAGE);
            load_chunk(sb, ps, m0, n0, t + 2, tid);
            cp_commit();
        }

#pragma unroll
        for (int ks = 0; ks < 4; ks++) {
            const int cur = ks & 1, nxt = cur ^ 1;
            if (ks < 3) {
                const uint32_t co = ((ks + 1) * 32 + csel) ^ xmask;
#pragma unroll
                for (int g = 0; g < 4; g++) ldsm4(stg + a_row[g] + co, a[nxt][g]);
#pragma unroll
                for (int g = 0; g < 4; g++) ldsm4(stg + b_row[g] + co, b[nxt][g]);
            }
#pragma unroll
            for (int i = 0; i < 4; i++)
#pragma unroll
                for (int j = 0; j < 8; j++)
                    mma16816(acc[i][j], a[cur][i],
                             b[cur][j >> 1][j & 1], b[cur][j >> 1][(j & 1) + 2]);
        }
    }

    // ---- fused epilogue (f32x2 exp; counts via histogram; raw-acc pos sums) ----
    int rowl[8], la[8];
#pragma unroll
    for (int i = 0; i < 4; i++)
#pragma unroll
        for (int h = 0; h < 2; h++) {
            int ri = i * 2 + h;
            rowl[ri] = wr * 64 + i * 16 + h * 8 + qr;
            la[ri] = lAs[rowl[ri]];
        }
    float rs[8], rp[8];
#pragma unroll
    for (int ri = 0; ri < 8; ri++) { rs[ri] = 0.f; rp[ri] = 0.f; }

    if (!diagTile) {
        // common path: no diag predicate anywhere
#pragma unroll
        for (int j = 0; j < 8; j++) {
            const int lc0 = wc * 64 + j * 8 + qc * 2;
            const int lc1 = lc0 + 1;
            const int lb0 = lBs[lc0], lb1 = lBs[lc1];
            float cs0 = 0.f, cp0 = 0.f, cs1 = 0.f, cp1 = 0.f;
#pragma unroll
            for (int i = 0; i < 4; i++)
#pragma unroll
                for (int h = 0; h < 2; h++) {
                    const int ri = i * 2 + h;
                    const float x0 = acc[i][j][h * 2], x1 = acc[i][j][h * 2 + 1];
                    float e0, e1;
                    fexp2(x0, x1, e0, e1);
                    rs[ri] += e0; cs0 += e0;
                    rs[ri] += e1; cs1 += e1;
                    const float m0v = (lb0 == la[ri]) ? x0 : 0.f;
                    const float m1v = (lb1 == la[ri]) ? x1 : 0.f;
                    rp[ri] += m0v; cp0 += m0v;
                    rp[ri] += m1v; cp1 += m1v;
                }
            // reduce across qr lanes (stride 4): 8 partials -> 1
#pragma unroll
            for (int o = 4; o <= 16; o <<= 1) {
                cs0 += __shfl_xor_sync(0xFFFFFFFFu, cs0, o);
                cp0 += __shfl_xor_sync(0xFFFFFFFFu, cp0, o);
                cs1 += __shfl_xor_sync(0xFFFFFFFFu, cs1, o);
                cp1 += __shfl_xor_sync(0xFFFFFFFFu, cp1, o);
            }
            if (qr == 0) {
                atomicAdd(&cS[lc0], cs0);
                atomicAdd(&cP[lc0], cp0);
                atomicAdd(&cS[lc1], cs1);
                atomicAdd(&cP[lc1], cp1);
            }
        }
    } else {
        // diagonal tile: predicate out self-pairs; no col stats
#pragma unroll
        for (int j = 0; j < 8; j++) {
            const int lc0 = wc * 64 + j * 8 + qc * 2;
            const int lc1 = lc0 + 1;
            const int lb0 = lBs[lc0], lb1 = lBs[lc1];
#pragma unroll
            for (int i = 0; i < 4; i++)
#pragma unroll
                for (int h = 0; h < 2; h++) {
                    const int ri = i * 2 + h;
                    const float x0 = acc[i][j][h * 2], x1 = acc[i][j][h * 2 + 1];
                    float e0, e1;
                    fexp2(x0, x1, e0, e1);
                    if (rowl[ri] != lc0) {
                        rs[ri] += e0;
                        if (lb0 == la[ri]) rp[ri] += x0;
                    }
                    if (rowl[ri] != lc1) {
                        rs[ri] += e1;
                        if (lb1 == la[ri]) rp[ri] += x1;
                    }
                }
        }
    }
    // reduce row stats across qc lanes (stride 1): 4 partials -> 1
#pragma unroll
    for (int ri = 0; ri < 8; ri++) {
#pragma unroll
        for (int o = 1; o <= 2; o <<= 1) {
            rs[ri] += __shfl_xor_sync(0xFFFFFFFFu, rs[ri], o);
            rp[ri] += __shfl_xor_sync(0xFFFFFFFFu, rp[ri], o);
        }
        if (qc == 0) {
            atomicAdd(&rS[rowl[ri]], rs[ri]);
            atomicAdd(&rP[rowl[ri]], rp[ri]);
        }
    }
    __syncthreads();

    if (tid < 128) {
        atomicAdd(&g_S[m0 + tid], rS[tid]);
        atomicAdd(&g_P[m0 + tid], rP[tid] * INV_TAU);
        atomicAdd(&g_C[m0 + tid], hB[lAs[tid] & 255] - (diagTile ? 1 : 0));
        if (!diagTile) {
            atomicAdd(&g_S[n0 + tid], cS[tid]);
            atomicAdd(&g_P[n0 + tid], cP[tid] * INV_TAU);
            atomicAdd(&g_C[n0 + tid], hA[lBs[tid] & 255]);
        }
    }
}

// 64 blocks x 128 threads; last block finalizes via ticket.
__global__ void reduce_kernel(float* __restrict__ out) {
    const int tid = threadIdx.x;
    const int r = blockIdx.x * 128 + tid;
    float loss = 0.f; int cnt = 0;
    const int c = g_C[r];
    if (c > 0) { loss = logf(g_S[r]) - g_P[r] / (float)c; cnt = 1; }
#pragma unroll
    for (int o = 16; o > 0; o >>= 1) {
        loss += __shfl_down_sync(0xFFFFFFFFu, loss, o);
        cnt  += __shfl_down_sync(0xFFFFFFFFu, cnt, o);
    }
    __shared__ float sl[4];
    __shared__ int   sc[4];
    if ((tid & 31) == 0) { sl[tid >> 5] = loss; sc[tid >> 5] = cnt; }
    __syncthreads();
    if (tid == 0) {
        float L = sl[0] + sl[1] + sl[2] + sl[3];
        int   C = sc[0] + sc[1] + sc[2] + sc[3];
        atomicAdd(&g_pl, L);
        atomicAdd(&g_pc, C);
        __threadfence();
        int prev = atomicAdd(&g_ticket, 1);
        if (prev == 63) {
            float tl = atomicAdd(&g_pl, 0.f);
            int   tc = atomicAdd(&g_pc, 0);
            out[0] = tl / (float)(tc > 0 ? tc : 1);
        }
    }
}

// ---------------- launch ----------------
extern "C" void kernel_launch(void* const* d_in, const int* in_sizes, int n_in,
                              void* d_out, int out_size) {
    const float*     E      = (const float*)d_in[0];
    const long long* labels = (const long long*)d_in[1];
    float*           out    = (float*)d_out;

    cudaFuncSetAttribute(sim_kernel, cudaFuncAttributeMaxDynamicSharedMemorySize, SMEM_TOTAL);

    convert_kernel<<<(B_SIZE * D_SIZE / 4) / 256, 256>>>(E);

    sim_kernel<<<NTILES, 128, SMEM_TOTAL>>>(labels);

    reduce_kernel<<<64, 128>>>(out);
}

// round 14
// speedup vs baseline: 1.3816x; 1.0018x over previous
#include <cuda_runtime.h>
#include <cuda_bf16.h>
#include <cstdint>

#define B_SIZE 8192
#define D_SIZE 1024
#define TM 128
#define TN 128
#define KC 64                      // bf16 elems per K-chunk (128 bytes/row)
#define NCHUNK (D_SIZE / KC)       // 16
#define NSTAGE 3
#define NOFFD 2016                 // 64*63/2 strictly-upper tiles
#define NTILES 2080                // + 64 diagonal tiles (scheduled last)
#define INV_TAU 10.0f

// ---------------- device scratch (no allocations allowed) ----------------
__device__ float g_S[B_SIZE];
__device__ float g_P[B_SIZE];
__device__ int   g_C[B_SIZE];
__device__ float g_pl;
__device__ int   g_pc;
__device__ int   g_ticket;
__device__ __align__(16) __nv_bfloat16 g_Ebf[B_SIZE * D_SIZE];

// ---------------- smem layout ----------------
#define STAGE_BYTES 32768          // A tile 16KB + B tile 16KB
#define OFF_B 16384
#define SM_MISC (NSTAGE * STAGE_BYTES)
#define SM_LA  (SM_MISC + 0)       // int[128]
#define SM_LB  (SM_MISC + 512)
#define SM_RS  (SM_MISC + 1024)    // float[128]
#define SM_RP  (SM_MISC + 1536)
#define SM_CS  (SM_MISC + 2048)
#define SM_CP  (SM_MISC + 2560)
#define SM_HA  (SM_MISC + 3072)    // int[256] label histogram of A rows
#define SM_HB  (SM_MISC + 4096)    // int[256] label histogram of B rows
#define SMEM_TOTAL (SM_MISC + 5120)

// ---------------- helpers ----------------
__device__ __forceinline__ uint32_t smem_u32(const void* p) {
    uint32_t a;
    asm("{ .reg .u64 t; cvta.to.shared.u64 t, %1; cvt.u32.u64 %0, t; }" : "=r"(a) : "l"(p));
    return a;
}
__device__ __forceinline__ void cp_async16(uint32_t dst, const void* src) {
    asm volatile("cp.async.cg.shared.global [%0], [%1], 16;" :: "r"(dst), "l"(src));
}
__device__ __forceinline__ void cp_commit() { asm volatile("cp.async.commit_group;"); }

__device__ __forceinline__ void ldsm4(uint32_t addr, uint32_t* r) {
    asm volatile("ldmatrix.sync.aligned.m8n8.x4.shared.b16 {%0,%1,%2,%3}, [%4];"
                 : "=r"(r[0]), "=r"(r[1]), "=r"(r[2]), "=r"(r[3]) : "r"(addr));
}
__device__ __forceinline__ void mma16816(float* d, const uint32_t* a,
                                         uint32_t b0, uint32_t b1) {
    asm volatile(
        "mma.sync.aligned.m16n8k16.row.col.f32.bf16.bf16.f32 "
        "{%0,%1,%2,%3}, {%4,%5,%6,%7}, {%8,%9}, {%0,%1,%2,%3};"
        : "+f"(d[0]), "+f"(d[1]), "+f"(d[2]), "+f"(d[3])
        : "r"(a[0]), "r"(a[1]), "r"(a[2]), "r"(a[3]), "r"(b0), "r"(b1));
}

// ---------------- packed f32x2 fast-exp ----------------
__device__ __forceinline__ uint64_t pack2(float x) {
    uint64_t r;
    asm("mov.b64 %0, {%1, %1};" : "=l"(r) : "f"(x));
    return r;
}
// e = exp(x * INV_TAU) for a pair of raw accumulator values.
__device__ __forceinline__ void fexp2(float x0, float x1, float& e0, float& e1) {
    const uint64_t cK    = pack2(14.426950408889634f);  // INV_TAU * log2(e)
    const uint64_t cMag  = pack2(12582912.0f);          // 1.5 * 2^23
    const uint64_t cNeg1 = pack2(-1.0f);
    const uint64_t c5 = pack2(1.3333558e-3f);
    const uint64_t c4 = pack2(9.6181291e-3f);
    const uint64_t c3 = pack2(5.5504109e-2f);
    const uint64_t c2 = pack2(2.4022650e-1f);
    const uint64_t c1 = pack2(6.9314718e-1f);
    const uint64_t cOne = pack2(1.0f);

    uint64_t x2, y2, t2, u2, f2, p2;
    asm("mov.b64 %0, {%1, %2};" : "=l"(x2) : "f"(x0), "f"(x1));
    asm("mul.rn.f32x2 %0, %1, %2;" : "=l"(y2) : "l"(x2), "l"(cK));
    asm("add.rn.f32x2 %0, %1, %2;" : "=l"(t2) : "l"(y2), "l"(cMag));
    asm("fma.rn.f32x2 %0, %1, %2, %3;" : "=l"(u2) : "l"(cMag), "l"(cNeg1), "l"(t2)); // t - MAGIC
    asm("fma.rn.f32x2 %0, %1, %2, %3;" : "=l"(f2) : "l"(u2), "l"(cNeg1), "l"(y2));   // y - (t-MAGIC)
    p2 = c5;
    asm("fma.rn.f32x2 %0, %1, %2, %3;" : "=l"(p2) : "l"(p2), "l"(f2), "l"(c4));
    asm("fma.rn.f32x2 %0, %1, %2, %3;" : "=l"(p2) : "l"(p2), "l"(f2), "l"(c3));
    asm("fma.rn.f32x2 %0, %1, %2, %3;" : "=l"(p2) : "l"(p2), "l"(f2), "l"(c2));
    asm("fma.rn.f32x2 %0, %1, %2, %3;" : "=l"(p2) : "l"(p2), "l"(f2), "l"(c1));
    asm("fma.rn.f32x2 %0, %1, %2, %3;" : "=l"(p2) : "l"(p2), "l"(f2), "l"(cOne));

    uint32_t tl, th, pl, ph;
    asm("mov.b64 {%0, %1}, %2;" : "=r"(tl), "=r"(th) : "l"(t2));
    asm("mov.b64 {%0, %1}, %2;" : "=r"(pl), "=r"(ph) : "l"(p2));
    // (tl - 0x4B400000) << 23 == tl << 23  (low 9 bits of the bias are zero)
    e0 = __int_as_float((int)(pl + (tl << 23)));
    e1 = __int_as_float((int)(ph + (th << 23)));
}

// ---------------- kernels ----------------
// 4 float4 per thread, loads batched first (MLP=4)
__global__ void convert_kernel(const float* __restrict__ E) {
    const int tid = threadIdx.x;
    const int zi = blockIdx.x * 256 + tid;
    if (zi < B_SIZE) { g_S[zi] = 0.f; g_P[zi] = 0.f; g_C[zi] = 0; }
    if (zi == 0) { g_pl = 0.f; g_pc = 0; g_ticket = 0; }

    const int base = blockIdx.x * 1024 + tid;
    const float4* Ep = reinterpret_cast<const float4*>(E);
    float4 v[4];
#pragma unroll
    for (int k = 0; k < 4; k++) v[k] = Ep[base + k * 256];
    __nv_bfloat162* hp = reinterpret_cast<__nv_bfloat162*>(g_Ebf);
#pragma unroll
    for (int k = 0; k < 4; k++) {
        const int idx = base + k * 256;
        hp[idx * 2 + 0] = __nv_bfloat162(__float2bfloat16(v[k].x), __float2bfloat16(v[k].y));
        hp[idx * 2 + 1] = __nv_bfloat162(__float2bfloat16(v[k].z), __float2bfloat16(v[k].w));
    }
}

__device__ __forceinline__ void load_chunk(uint32_t sb, int stage, int m0, int n0,
                                           int chunk, int tid) {
    const char* eb = reinterpret_cast<const char*>(g_Ebf);
    uint32_t sbase = sb + stage * STAGE_BYTES;
    size_t colb = (size_t)chunk * 128;
#pragma unroll
    for (int q = 0; q < 8; q++) {
        int idx = tid + q * 128;        // 0..1023
        int row = idx >> 3;             // 0..127
        int c16 = idx & 7;
        uint32_t sw = row * 128 + ((c16 * 16) ^ ((row & 7) << 4));
        size_t gA = (size_t)(m0 + row) * 2048 + colb + c16 * 16;
        size_t gB = (size_t)(n0 + row) * 2048 + colb + c16 * 16;
        cp_async16(sbase + sw, eb + gA);
        cp_async16(sbase + OFF_B + sw, eb + gB);
    }
}

__global__ void __launch_bounds__(128, 2)
sim_kernel(const long long* __restrict__ labels) {
    // l < NOFFD: strictly-upper (bi < bj); l >= NOFFD: diagonal tiles (cheap, last)
    const int l = blockIdx.x;
    int bi, bj;
    if (l < NOFFD) {
        int g = (int)(63.5f - sqrtf(fmaxf(63.5f * 63.5f - 2.0f * (float)l, 0.f)));
        if (g > 62) g = 62;
        if (g < 0) g = 0;
        while (g > 0 && 63 * g - (g * (g - 1)) / 2 > l) g--;
        while (63 * (g + 1) - ((g + 1) * g) / 2 <= l) g++;
        bi = g;
        bj = g + 1 + (l - (63 * g - (g * (g - 1)) / 2));
    } else {
        bi = bj = l - NOFFD;
    }

    extern __shared__ char smem[];
    const uint32_t sb = smem_u32(smem);
    const int tid = threadIdx.x;
    const int wid = tid >> 5, lane = tid & 31;
    const int m0 = bi * TM, n0 = bj * TN;
    const bool diagTile = (bi == bj);

    int*   lAs = reinterpret_cast<int*>(smem + SM_LA);
    int*   lBs = reinterpret_cast<int*>(smem + SM_LB);
    float* rS = reinterpret_cast<float*>(smem + SM_RS);
    float* rP = reinterpret_cast<float*>(smem + SM_RP);
    float* cS = reinterpret_cast<float*>(smem + SM_CS);
    float* cP = reinterpret_cast<float*>(smem + SM_CP);
    int*   hA = reinterpret_cast<int*>(smem + SM_HA);
    int*   hB = reinterpret_cast<int*>(smem + SM_HB);

    load_chunk(sb, 0, m0, n0, 0, tid); cp_commit();
    load_chunk(sb, 1, m0, n0, 1, tid); cp_commit();

    if (tid < 128) {
        lAs[tid] = (int)labels[m0 + tid];
        lBs[tid] = (int)labels[n0 + tid];
        rS[tid] = 0.f; rP[tid] = 0.f;
        cS[tid] = 0.f; cP[tid] = 0.f;
        hA[tid] = 0; hA[tid + 128] = 0;
        hB[tid] = 0; hB[tid + 128] = 0;
    }
    __syncthreads();
    if (tid < 128) {
        atomicAdd(&hA[lAs[tid] & 255], 1);
        atomicAdd(&hB[lBs[tid] & 255], 1);
    }

    // 4 warps, 2x2; warp tile = 64 rows x 64 cols
    const int wr = wid >> 1, wc = wid & 1;
    const int qr = lane >> 2, qc = lane & 3;
    const uint32_t xmask = (lane & 7) << 4;
    const uint32_t rsel = lane & 15;
    const uint32_t csel = (lane >> 4) << 4;
    uint32_t a_row[4], b_row[4];
#pragma unroll
    for (int g = 0; g < 4; g++) {
        a_row[g] = (wr * 64 + g * 16 + rsel) * 128;
        b_row[g] = (wc * 64 + g * 16 + rsel) * 128 + OFF_B;
    }

    float acc[4][8][4];
#pragma unroll
    for (int i = 0; i < 4; i++)
#pragma unroll
        for (int j = 0; j < 8; j++)
#pragma unroll
            for (int k = 0; k < 4; k++) acc[i][j][k] = 0.f;

    uint32_t a[2][4][4], b[2][4][4];   // register double buffer
    int st = 0;                        // consuming stage (t % 3), tracked

    for (int t = 0; t < NCHUNK; t++) {
        if (t < NCHUNK - 1) asm volatile("cp.async.wait_group 1;" ::: "memory");
        else                asm volatile("cp.async.wait_group 0;" ::: "memory");
        __syncthreads();

        const uint32_t stg = sb + st * STAGE_BYTES;

        // preload ks=0 fragments
        {
            const uint32_t co = csel ^ xmask;
#pragma unroll
            for (int g = 0; g < 4; g++) ldsm4(stg + a_row[g] + co, a[0][g]);
#pragma unroll
            for (int g = 0; g < 4; g++) ldsm4(stg + b_row[g] + co, b[0][g]);
        }

        // prefetch chunk t+2 into stage (t+2)%3 == st-1 mod 3
        if (t + 2 < NCHUNK) {
            int ps = st - 1; if (ps < 0) ps += NSTAGE;
            load_chunk(sb, ps, m0, n0, t + 2, tid);
            cp_commit();
        }

#pragma unroll
        for (int ks = 0; ks < 4; ks++) {
            const int cur = ks & 1, nxt = cur ^ 1;
            if (ks < 3) {
                const uint32_t co = ((ks + 1) * 32 + csel) ^ xmask;
#pragma unroll
                for (int g = 0; g < 4; g++) ldsm4(stg + a_row[g] + co, a[nxt][g]);
#pragma unroll
                for (int g = 0; g < 4; g++) ldsm4(stg + b_row[g] + co, b[nxt][g]);
            }
#pragma unroll
            for (int i = 0; i < 4; i++)
#pragma unroll
                for (int j = 0; j < 8; j++)
                    mma16816(acc[i][j], a[cur][i],
                             b[cur][j >> 1][j & 1], b[cur][j >> 1][(j & 1) + 2]);
        }
        st++; if (st == NSTAGE) st = 0;
    }

    // ---- fused epilogue (f32x2 exp; counts via histogram; raw-acc pos sums) ----
    int rowl[8], la[8];
#pragma unroll
    for (int i = 0; i < 4; i++)
#pragma unroll
        for (int h = 0; h < 2; h++) {
            int ri = i * 2 + h;
            rowl[ri] = wr * 64 + i * 16 + h * 8 + qr;
            la[ri] = lAs[rowl[ri]];
        }
    float rs[8], rp[8];
#pragma unroll
    for (int ri = 0; ri < 8; ri++) { rs[ri] = 0.f; rp[ri] = 0.f; }

    if (!diagTile) {
        // common path: no diag predicate anywhere
#pragma unroll
        for (int j = 0; j < 8; j++) {
            const int lc0 = wc * 64 + j * 8 + qc * 2;
            const int lc1 = lc0 + 1;
            const int lb0 = lBs[lc0], lb1 = lBs[lc1];
            float cs0 = 0.f, cp0 = 0.f, cs1 = 0.f, cp1 = 0.f;
#pragma unroll
            for (int i = 0; i < 4; i++)
#pragma unroll
                for (int h = 0; h < 2; h++) {
                    const int ri = i * 2 + h;
                    const float x0 = acc[i][j][h * 2], x1 = acc[i][j][h * 2 + 1];
                    float e0, e1;
                    fexp2(x0, x1, e0, e1);
                    rs[ri] += e0; cs0 += e0;
                    rs[ri] += e1; cs1 += e1;
                    const float m0v = (lb0 == la[ri]) ? x0 : 0.f;
                    const float m1v = (lb1 == la[ri]) ? x1 : 0.f;
                    rp[ri] += m0v; cp0 += m0v;
                    rp[ri] += m1v; cp1 += m1v;
                }
            // reduce across qr lanes (stride 4): 8 partials -> 1
#pragma unroll
            for (int o = 4; o <= 16; o <<= 1) {
                cs0 += __shfl_xor_sync(0xFFFFFFFFu, cs0, o);
                cp0 += __shfl_xor_sync(0xFFFFFFFFu, cp0, o);
                cs1 += __shfl_xor_sync(0xFFFFFFFFu, cs1, o);
                cp1 += __shfl_xor_sync(0xFFFFFFFFu, cp1, o);
            }
            if (qr == 0) {
                atomicAdd(&cS[lc0], cs0);
                atomicAdd(&cP[lc0], cp0);
                atomicAdd(&cS[lc1], cs1);
                atomicAdd(&cP[lc1], cp1);
            }
        }
    } else {
        // diagonal tile: predicate out self-pairs; no col stats
#pragma unroll
        for (int j = 0; j < 8; j++) {
            const int lc0 = wc * 64 + j * 8 + qc * 2;
            const int lc1 = lc0 + 1;
            const int lb0 = lBs[lc0], lb1 = lBs[lc1];
#pragma unroll
            for (int i = 0; i < 4; i++)
#pragma unroll
                for (int h = 0; h < 2; h++) {
                    const int ri = i * 2 + h;
                    const float x0 = acc[i][j][h * 2], x1 = acc[i][j][h * 2 + 1];
                    float e0, e1;
                    fexp2(x0, x1, e0, e1);
                    if (rowl[ri] != lc0) {
                        rs[ri] += e0;
                        if (lb0 == la[ri]) rp[ri] += x0;
                    }
                    if (rowl[ri] != lc1) {
                        rs[ri] += e1;
                        if (lb1 == la[ri]) rp[ri] += x1;
                    }
                }
        }
    }
    // reduce row stats across qc lanes (stride 1): 4 partials -> 1
#pragma unroll
    for (int ri = 0; ri < 8; ri++) {
#pragma unroll
        for (int o = 1; o <= 2; o <<= 1) {
            rs[ri] += __shfl_xor_sync(0xFFFFFFFFu, rs[ri], o);
            rp[ri] += __shfl_xor_sync(0xFFFFFFFFu, rp[ri], o);
        }
        if (qc == 0) {
            atomicAdd(&rS[rowl[ri]], rs[ri]);
            atomicAdd(&rP[rowl[ri]], rp[ri]);
        }
    }
    __syncthreads();

    if (tid < 128) {
        atomicAdd(&g_S[m0 + tid], rS[tid]);
        atomicAdd(&g_P[m0 + tid], rP[tid] * INV_TAU);
        atomicAdd(&g_C[m0 + tid], hB[lAs[tid] & 255] - (diagTile ? 1 : 0));
        if (!diagTile) {
            atomicAdd(&g_S[n0 + tid], cS[tid]);
            atomicAdd(&g_P[n0 + tid], cP[tid] * INV_TAU);
            atomicAdd(&g_C[n0 + tid], hA[lBs[tid] & 255]);
        }
    }
}

// 64 blocks x 128 threads; last block finalizes via ticket.
__global__ void reduce_kernel(float* __restrict__ out) {
    const int tid = threadIdx.x;
    const int r = blockIdx.x * 128 + tid;
    float loss = 0.f; int cnt = 0;
    const int c = g_C[r];
    if (c > 0) { loss = logf(g_S[r]) - g_P[r] / (float)c; cnt = 1; }
#pragma unroll
    for (int o = 16; o > 0; o >>= 1) {
        loss += __shfl_down_sync(0xFFFFFFFFu, loss, o);
        cnt  += __shfl_down_sync(0xFFFFFFFFu, cnt, o);
    }
    __shared__ float sl[4];
    __shared__ int   sc[4];
    if ((tid & 31) == 0) { sl[tid >> 5] = loss; sc[tid >> 5] = cnt; }
    __syncthreads();
    if (tid == 0) {
        float L = sl[0] + sl[1] + sl[2] + sl[3];
        int   C = sc[0] + sc[1] + sc[2] + sc[3];
        atomicAdd(&g_pl, L);
        atomicAdd(&g_pc, C);
        __threadfence();
        int prev = atomicAdd(&g_ticket, 1);
        if (prev == 63) {
            float tl = atomicAdd(&g_pl, 0.f);
            int   tc = atomicAdd(&g_pc, 0);
            out[0] = tl / (float)(tc > 0 ? tc : 1);
        }
    }
}

// ---------------- launch ----------------
extern "C" void kernel_launch(void* const* d_in, const int* in_sizes, int n_in,
                              void* d_out, int out_size) {
    const float*     E      = (const float*)d_in[0];
    const long long* labels = (const long long*)d_in[1];
    float*           out    = (float*)d_out;

    cudaFuncSetAttribute(sim_kernel, cudaFuncAttributeMaxDynamicSharedMemorySize, SMEM_TOTAL);

    convert_kernel<<<(B_SIZE * D_SIZE / 4) / 1024, 256>>>(E);

    sim_kernel<<<NTILES, 128, SMEM_TOTAL>>>(labels);

    reduce_kernel<<<64, 128>>>(out);
}

// round 15
// speedup vs baseline: 1.4368x; 1.0400x over previous
#include <cuda_runtime.h>
#include <cuda_fp16.h>
#include <cstdint>

#define B_SIZE 8192
#define D_SIZE 1024
#define TM 128
#define TN 128
#define KC 64                      // fp16 elems per K-chunk (128 bytes/row)
#define NCHUNK (D_SIZE / KC)       // 16
#define NSTAGE 3
#define NOFFD 2016                 // 64*63/2 strictly-upper tiles
#define NTILES 2080                // + 64 diagonal tiles (scheduled last)
#define INV_TAU 10.0f

// ---------------- device scratch (no allocations allowed) ----------------
__device__ float g_S[B_SIZE];
__device__ float g_P[B_SIZE];
__device__ int   g_C[B_SIZE];
__device__ float g_pl;
__device__ int   g_pc;
__device__ int   g_ticket;
__device__ __align__(16) __half g_Ehf[B_SIZE * D_SIZE];

// ---------------- smem layout ----------------
#define STAGE_BYTES 32768          // A tile 16KB + B tile 16KB
#define OFF_B 16384
#define SM_MISC (NSTAGE * STAGE_BYTES)
#define SM_LA  (SM_MISC + 0)       // int[128]
#define SM_LB  (SM_MISC + 512)
#define SM_RS  (SM_MISC + 1024)    // float[128]
#define SM_RP  (SM_MISC + 1536)
#define SM_CS  (SM_MISC + 2048)
#define SM_CP  (SM_MISC + 2560)
#define SM_HA  (SM_MISC + 3072)    // int[256] label histogram of A rows
#define SM_HB  (SM_MISC + 4096)    // int[256] label histogram of B rows
#define SMEM_TOTAL (SM_MISC + 5120)

// ---------------- helpers ----------------
__device__ __forceinline__ uint32_t smem_u32(const void* p) {
    uint32_t a;
    asm("{ .reg .u64 t; cvta.to.shared.u64 t, %1; cvt.u32.u64 %0, t; }" : "=r"(a) : "l"(p));
    return a;
}
__device__ __forceinline__ void cp_async16(uint32_t dst, const void* src) {
    asm volatile("cp.async.cg.shared.global [%0], [%1], 16;" :: "r"(dst), "l"(src));
}
__device__ __forceinline__ void cp_commit() { asm volatile("cp.async.commit_group;"); }

__device__ __forceinline__ void ldsm4(uint32_t addr, uint32_t* r) {
    asm volatile("ldmatrix.sync.aligned.m8n8.x4.shared.b16 {%0,%1,%2,%3}, [%4];"
                 : "=r"(r[0]), "=r"(r[1]), "=r"(r[2]), "=r"(r[3]) : "r"(addr));
}
// fp16 in, fp16 accumulate: d = {c0c1, c2c3} packed half2
__device__ __forceinline__ void mma16816h(uint32_t* d, const uint32_t* a,
                                          uint32_t b0, uint32_t b1) {
    asm volatile(
        "mma.sync.aligned.m16n8k16.row.col.f16.f16.f16.f16 "
        "{%0,%1}, {%2,%3,%4,%5}, {%6,%7}, {%0,%1};"
        : "+r"(d[0]), "+r"(d[1])
        : "r"(a[0]), "r"(a[1]), "r"(a[2]), "r"(a[3]), "r"(b0), "r"(b1));
}

// ---------------- packed f32x2 fast-exp ----------------
__device__ __forceinline__ uint64_t pack2(float x) {
    uint64_t r;
    asm("mov.b64 %0, {%1, %1};" : "=l"(r) : "f"(x));
    return r;
}
// e = exp(x * INV_TAU) for a pair of raw accumulator values.
__device__ __forceinline__ void fexp2(float x0, float x1, float& e0, float& e1) {
    const uint64_t cK    = pack2(14.426950408889634f);  // INV_TAU * log2(e)
    const uint64_t cMag  = pack2(12582912.0f);          // 1.5 * 2^23
    const uint64_t cNeg1 = pack2(-1.0f);
    const uint64_t c5 = pack2(1.3333558e-3f);
    const uint64_t c4 = pack2(9.6181291e-3f);
    const uint64_t c3 = pack2(5.5504109e-2f);
    const uint64_t c2 = pack2(2.4022650e-1f);
    const uint64_t c1 = pack2(6.9314718e-1f);
    const uint64_t cOne = pack2(1.0f);

    uint64_t x2, y2, t2, u2, f2, p2;
    asm("mov.b64 %0, {%1, %2};" : "=l"(x2) : "f"(x0), "f"(x1));
    asm("mul.rn.f32x2 %0, %1, %2;" : "=l"(y2) : "l"(x2), "l"(cK));
    asm("add.rn.f32x2 %0, %1, %2;" : "=l"(t2) : "l"(y2), "l"(cMag));
    asm("fma.rn.f32x2 %0, %1, %2, %3;" : "=l"(u2) : "l"(cMag), "l"(cNeg1), "l"(t2)); // t - MAGIC
    asm("fma.rn.f32x2 %0, %1, %2, %3;" : "=l"(f2) : "l"(u2), "l"(cNeg1), "l"(y2));   // y - (t-MAGIC)
    p2 = c5;
    asm("fma.rn.f32x2 %0, %1, %2, %3;" : "=l"(p2) : "l"(p2), "l"(f2), "l"(c4));
    asm("fma.rn.f32x2 %0, %1, %2, %3;" : "=l"(p2) : "l"(p2), "l"(f2), "l"(c3));
    asm("fma.rn.f32x2 %0, %1, %2, %3;" : "=l"(p2) : "l"(p2), "l"(f2), "l"(c2));
    asm("fma.rn.f32x2 %0, %1, %2, %3;" : "=l"(p2) : "l"(p2), "l"(f2), "l"(c1));
    asm("fma.rn.f32x2 %0, %1, %2, %3;" : "=l"(p2) : "l"(p2), "l"(f2), "l"(cOne));

    uint32_t tl, th, pl, ph;
    asm("mov.b64 {%0, %1}, %2;" : "=r"(tl), "=r"(th) : "l"(t2));
    asm("mov.b64 {%0, %1}, %2;" : "=r"(pl), "=r"(ph) : "l"(p2));
    // (tl - 0x4B400000) << 23 == tl << 23  (low 9 bits of the bias are zero)
    e0 = __int_as_float((int)(pl + (tl << 23)));
    e1 = __int_as_float((int)(ph + (th << 23)));
}

// ---------------- kernels ----------------
// 4 float4 per thread, loads batched first (MLP=4); fp32 -> fp16
__global__ void convert_kernel(const float* __restrict__ E) {
    const int tid = threadIdx.x;
    const int zi = blockIdx.x * 256 + tid;
    if (zi < B_SIZE) { g_S[zi] = 0.f; g_P[zi] = 0.f; g_C[zi] = 0; }
    if (zi == 0) { g_pl = 0.f; g_pc = 0; g_ticket = 0; }

    const int base = blockIdx.x * 1024 + tid;
    const float4* Ep = reinterpret_cast<const float4*>(E);
    float4 v[4];
#pragma unroll
    for (int k = 0; k < 4; k++) v[k] = Ep[base + k * 256];
    __half2* hp = reinterpret_cast<__half2*>(g_Ehf);
#pragma unroll
    for (int k = 0; k < 4; k++) {
        const int idx = base + k * 256;
        hp[idx * 2 + 0] = __floats2half2_rn(v[k].x, v[k].y);
        hp[idx * 2 + 1] = __floats2half2_rn(v[k].z, v[k].w);
    }
}

__device__ __forceinline__ void load_chunk(uint32_t sb, int stage, int m0, int n0,
                                           int chunk, int tid) {
    const char* eb = reinterpret_cast<const char*>(g_Ehf);
    uint32_t sbase = sb + stage * STAGE_BYTES;
    size_t colb = (size_t)chunk * 128;
#pragma unroll
    for (int q = 0; q < 8; q++) {
        int idx = tid + q * 128;        // 0..1023
        int row = idx >> 3;             // 0..127
        int c16 = idx & 7;
        uint32_t sw = row * 128 + ((c16 * 16) ^ ((row & 7) << 4));
        size_t gA = (size_t)(m0 + row) * 2048 + colb + c16 * 16;
        size_t gB = (size_t)(n0 + row) * 2048 + colb + c16 * 16;
        cp_async16(sbase + sw, eb + gA);
        cp_async16(sbase + OFF_B + sw, eb + gB);
    }
}

__global__ void __launch_bounds__(128, 2)
sim_kernel(const long long* __restrict__ labels) {
    // l < NOFFD: strictly-upper (bi < bj); l >= NOFFD: diagonal tiles (cheap, last)
    const int l = blockIdx.x;
    int bi, bj;
    if (l < NOFFD) {
        int g = (int)(63.5f - sqrtf(fmaxf(63.5f * 63.5f - 2.0f * (float)l, 0.f)));
        if (g > 62) g = 62;
        if (g < 0) g = 0;
        while (g > 0 && 63 * g - (g * (g - 1)) / 2 > l) g--;
        while (63 * (g + 1) - ((g + 1) * g) / 2 <= l) g++;
        bi = g;
        bj = g + 1 + (l - (63 * g - (g * (g - 1)) / 2));
    } else {
        bi = bj = l - NOFFD;
    }

    extern __shared__ char smem[];
    const uint32_t sb = smem_u32(smem);
    const int tid = threadIdx.x;
    const int wid = tid >> 5, lane = tid & 31;
    const int m0 = bi * TM, n0 = bj * TN;
    const bool diagTile = (bi == bj);

    int*   lAs = reinterpret_cast<int*>(smem + SM_LA);
    int*   lBs = reinterpret_cast<int*>(smem + SM_LB);
    float* rS = reinterpret_cast<float*>(smem + SM_RS);
    float* rP = reinterpret_cast<float*>(smem + SM_RP);
    float* cS = reinterpret_cast<float*>(smem + SM_CS);
    float* cP = reinterpret_cast<float*>(smem + SM_CP);
    int*   hA = reinterpret_cast<int*>(smem + SM_HA);
    int*   hB = reinterpret_cast<int*>(smem + SM_HB);

    load_chunk(sb, 0, m0, n0, 0, tid); cp_commit();
    load_chunk(sb, 1, m0, n0, 1, tid); cp_commit();

    if (tid < 128) {
        lAs[tid] = (int)labels[m0 + tid];
        lBs[tid] = (int)labels[n0 + tid];
        rS[tid] = 0.f; rP[tid] = 0.f;
        cS[tid] = 0.f; cP[tid] = 0.f;
        hA[tid] = 0; hA[tid + 128] = 0;
        hB[tid] = 0; hB[tid + 128] = 0;
    }
    __syncthreads();
    if (tid < 128) {
        atomicAdd(&hA[lAs[tid] & 255], 1);
        atomicAdd(&hB[lBs[tid] & 255], 1);
    }

    // 4 warps, 2x2; warp tile = 64 rows x 64 cols
    const int wr = wid >> 1, wc = wid & 1;
    const int qr = lane >> 2, qc = lane & 3;
    const uint32_t xmask = (lane & 7) << 4;
    const uint32_t rsel = lane & 15;
    const uint32_t csel = (lane >> 4) << 4;
    uint32_t a_row[4], b_row[4];
#pragma unroll
    for (int g = 0; g < 4; g++) {
        a_row[g] = (wr * 64 + g * 16 + rsel) * 128;
        b_row[g] = (wc * 64 + g * 16 + rsel) * 128 + OFF_B;
    }

    // fp16x2 accumulators: acc[i][j][h] packs cols (cc=0,1) of row-group h
    uint32_t acc[4][8][2];
#pragma unroll
    for (int i = 0; i < 4; i++)
#pragma unroll
        for (int j = 0; j < 8; j++) { acc[i][j][0] = 0u; acc[i][j][1] = 0u; }

    uint32_t a[2][4][4], b[2][4][4];   // register double buffer
    int st = 0;                        // consuming stage (t % 3), tracked

    for (int t = 0; t < NCHUNK; t++) {
        if (t < NCHUNK - 1) asm volatile("cp.async.wait_group 1;" ::: "memory");
        else                asm volatile("cp.async.wait_group 0;" ::: "memory");
        __syncthreads();

        const uint32_t stg = sb + st * STAGE_BYTES;

        // preload ks=0 fragments
        {
            const uint32_t co = csel ^ xmask;
#pragma unroll
            for (int g = 0; g < 4; g++) ldsm4(stg + a_row[g] + co, a[0][g]);
#pragma unroll
            for (int g = 0; g < 4; g++) ldsm4(stg + b_row[g] + co, b[0][g]);
        }

        // prefetch chunk t+2 into stage (t+2)%3 == st-1 mod 3
        if (t + 2 < NCHUNK) {
            int ps = st - 1; if (ps < 0) ps += NSTAGE;
            load_chunk(sb, ps, m0, n0, t + 2, tid);
            cp_commit();
        }

#pragma unroll
        for (int ks = 0; ks < 4; ks++) {
            const int cur = ks & 1, nxt = cur ^ 1;
            if (ks < 3) {
                const uint32_t co = ((ks + 1) * 32 + csel) ^ xmask;
#pragma unroll
                for (int g = 0; g < 4; g++) ldsm4(stg + a_row[g] + co, a[nxt][g]);
#pragma unroll
                for (int g = 0; g < 4; g++) ldsm4(stg + b_row[g] + co, b[nxt][g]);
            }
#pragma unroll
            for (int i = 0; i < 4; i++)
#pragma unroll
                for (int j = 0; j < 8; j++)
                    mma16816h(acc[i][j], a[cur][i],
                              b[cur][j >> 1][j & 1], b[cur][j >> 1][(j & 1) + 2]);
        }
        st++; if (st == NSTAGE) st = 0;
    }

    // ---- fused epilogue (f32x2 exp; counts via histogram; raw-acc pos sums) ----
    int rowl[8], la[8];
#pragma unroll
    for (int i = 0; i < 4; i++)
#pragma unroll
        for (int h = 0; h < 2; h++) {
            int ri = i * 2 + h;
            rowl[ri] = wr * 64 + i * 16 + h * 8 + qr;
            la[ri] = lAs[rowl[ri]];
        }
    float rs[8], rp[8];
#pragma unroll
    for (int ri = 0; ri < 8; ri++) { rs[ri] = 0.f; rp[ri] = 0.f; }

    if (!diagTile) {
        // common path: no diag predicate anywhere
#pragma unroll
        for (int j = 0; j < 8; j++) {
            const int lc0 = wc * 64 + j * 8 + qc * 2;
            const int lc1 = lc0 + 1;
            const int lb0 = lBs[lc0], lb1 = lBs[lc1];
            float cs0 = 0.f, cp0 = 0.f, cs1 = 0.f, cp1 = 0.f;
#pragma unroll
            for (int i = 0; i < 4; i++)
#pragma unroll
                for (int h = 0; h < 2; h++) {
                    const int ri = i * 2 + h;
                    const float2 xv = __half22float2(
                        *reinterpret_cast<const __half2*>(&acc[i][j][h]));
                    const float x0 = xv.x, x1 = xv.y;
                    float e0, e1;
                    fexp2(x0, x1, e0, e1);
                    rs[ri] += e0; cs0 += e0;
                    rs[ri] += e1; cs1 += e1;
                    const float m0v = (lb0 == la[ri]) ? x0 : 0.f;
                    const float m1v = (lb1 == la[ri]) ? x1 : 0.f;
                    rp[ri] += m0v; cp0 += m0v;
                    rp[ri] += m1v; cp1 += m1v;
                }
            // reduce across qr lanes (stride 4): 8 partials -> 1
#pragma unroll
            for (int o = 4; o <= 16; o <<= 1) {
                cs0 += __shfl_xor_sync(0xFFFFFFFFu, cs0, o);
                cp0 += __shfl_xor_sync(0xFFFFFFFFu, cp0, o);
                cs1 += __shfl_xor_sync(0xFFFFFFFFu, cs1, o);
                cp1 += __shfl_xor_sync(0xFFFFFFFFu, cp1, o);
            }
            if (qr == 0) {
                atomicAdd(&cS[lc0], cs0);
                atomicAdd(&cP[lc0], cp0);
                atomicAdd(&cS[lc1], cs1);
                atomicAdd(&cP[lc1], cp1);
            }
        }
    } else {
        // diagonal tile: predicate out self-pairs; no col stats
#pragma unroll
        for (int j = 0; j < 8; j++) {
            const int lc0 = wc * 64 + j * 8 + qc * 2;
            const int lc1 = lc0 + 1;
            const int lb0 = lBs[lc0], lb1 = lBs[lc1];
#pragma unroll
            for (int i = 0; i < 4; i++)
#pragma unroll
                for (int h = 0; h < 2; h++) {
                    const int ri = i * 2 + h;
                    const float2 xv = __half22float2(
                        *reinterpret_cast<const __half2*>(&acc[i][j][h]));
                    const float x0 = xv.x, x1 = xv.y;
                    float e0, e1;
                    fexp2(x0, x1, e0, e1);
                    if (rowl[ri] != lc0) {
                        rs[ri] += e0;
                        if (lb0 == la[ri]) rp[ri] += x0;
                    }
                    if (rowl[ri] != lc1) {
                        rs[ri] += e1;
                        if (lb1 == la[ri]) rp[ri] += x1;
                    }
                }
        }
    }
    // reduce row stats across qc lanes (stride 1): 4 partials -> 1
#pragma unroll
    for (int ri = 0; ri < 8; ri++) {
#pragma unroll
        for (int o = 1; o <= 2; o <<= 1) {
            rs[ri] += __shfl_xor_sync(0xFFFFFFFFu, rs[ri], o);
            rp[ri] += __shfl_xor_sync(0xFFFFFFFFu, rp[ri], o);
        }
        if (qc == 0) {
            atomicAdd(&rS[rowl[ri]], rs[ri]);
            atomicAdd(&rP[rowl[ri]], rp[ri]);
        }
    }
    __syncthreads();

    if (tid < 128) {
        atomicAdd(&g_S[m0 + tid], rS[tid]);
        atomicAdd(&g_P[m0 + tid], rP[tid] * INV_TAU);
        atomicAdd(&g_C[m0 + tid], hB[lAs[tid] & 255] - (diagTile ? 1 : 0));
        if (!diagTile) {
            atomicAdd(&g_S[n0 + tid], cS[tid]);
            atomicAdd(&g_P[n0 + tid], cP[tid] * INV_TAU);
            atomicAdd(&g_C[n0 + tid], hA[lBs[tid] & 255]);
        }
    }
}

// 64 blocks x 128 threads; last block finalizes via ticket.
__global__ void reduce_kernel(float* __restrict__ out) {
    const int tid = threadIdx.x;
    const int r = blockIdx.x * 128 + tid;
    float loss = 0.f; int cnt = 0;
    const int c = g_C[r];
    if (c > 0) { loss = logf(g_S[r]) - g_P[r] / (float)c; cnt = 1; }
#pragma unroll
    for (int o = 16; o > 0; o >>= 1) {
        loss += __shfl_down_sync(0xFFFFFFFFu, loss, o);
        cnt  += __shfl_down_sync(0xFFFFFFFFu, cnt, o);
    }
    __shared__ float sl[4];
    __shared__ int   sc[4];
    if ((tid & 31) == 0) { sl[tid >> 5] = loss; sc[tid >> 5] = cnt; }
    __syncthreads();
    if (tid == 0) {
        float L = sl[0] + sl[1] + sl[2] + sl[3];
        int   C = sc[0] + sc[1] + sc[2] + sc[3];
        atomicAdd(&g_pl, L);
        atomicAdd(&g_pc, C);
        __threadfence();
        int prev = atomicAdd(&g_ticket, 1);
        if (prev == 63) {
            float tl = atomicAdd(&g_pl, 0.f);
            int   tc = atomicAdd(&g_pc, 0);
            out[0] = tl / (float)(tc > 0 ? tc : 1);
        }
    }
}

// ---------------- launch ----------------
extern "C" void kernel_launch(void* const* d_in, const int* in_sizes, int n_in,
                              void* d_out, int out_size) {
    const float*     E      = (const float*)d_in[0];
    const long long* labels = (const long long*)d_in[1];
    float*           out    = (float*)d_out;

    cudaFuncSetAttribute(sim_kernel, cudaFuncAttributeMaxDynamicSharedMemorySize, SMEM_TOTAL);

    convert_kernel<<<(B_SIZE * D_SIZE / 4) / 1024, 256>>>(E);

    sim_kernel<<<NTILES, 128, SMEM_TOTAL>>>(labels);

    reduce_kernel<<<64, 128>>>(out);
}

// round 16
// speedup vs baseline: 1.5927x; 1.1085x over previous
#include <cuda_runtime.h>
#include <cuda_fp16.h>
#include <cstdint>

#define B_SIZE 8192
#define D_SIZE 1024
#define TM 128
#define TN 128
#define KC 64                      // fp16 elems per K-chunk (128 bytes/row)
#define NCHUNK (D_SIZE / KC)       // 16
#define NSTAGE 2
#define NOFFD 2016                 // 64*63/2 strictly-upper tiles
#define NTILES 2080                // + 64 diagonal tiles (scheduled last)
#define INV_TAU 10.0f

// ---------------- device scratch (no allocations allowed) ----------------
__device__ float g_S[B_SIZE];
__device__ float g_P[B_SIZE];
__device__ int   g_C[B_SIZE];
__device__ float g_pl;
__device__ int   g_pc;
__device__ int   g_ticket;
__device__ __align__(16) __half g_Ehf[B_SIZE * D_SIZE];

// ---------------- smem layout ----------------
#define STAGE_BYTES 32768          // A tile 16KB + B tile 16KB
#define OFF_B 16384
#define SM_MISC (NSTAGE * STAGE_BYTES)
#define SM_LA  (SM_MISC + 0)       // int[128]
#define SM_LB  (SM_MISC + 512)
#define SM_RS  (SM_MISC + 1024)    // float[128]
#define SM_RP  (SM_MISC + 1536)
#define SM_CS  (SM_MISC + 2048)
#define SM_CP  (SM_MISC + 2560)
#define SM_HA  (SM_MISC + 3072)    // int[256] label histogram of A rows
#define SM_HB  (SM_MISC + 4096)    // int[256] label histogram of B rows
#define SMEM_TOTAL (SM_MISC + 5120)

// ---------------- helpers ----------------
__device__ __forceinline__ uint32_t smem_u32(const void* p) {
    uint32_t a;
    asm("{ .reg .u64 t; cvta.to.shared.u64 t, %1; cvt.u32.u64 %0, t; }" : "=r"(a) : "l"(p));
    return a;
}
__device__ __forceinline__ void cp_async16(uint32_t dst, const void* src) {
    asm volatile("cp.async.cg.shared.global [%0], [%1], 16;" :: "r"(dst), "l"(src));
}
__device__ __forceinline__ void cp_commit() { asm volatile("cp.async.commit_group;"); }

__device__ __forceinline__ void ldsm4(uint32_t addr, uint32_t* r) {
    asm volatile("ldmatrix.sync.aligned.m8n8.x4.shared.b16 {%0,%1,%2,%3}, [%4];"
                 : "=r"(r[0]), "=r"(r[1]), "=r"(r[2]), "=r"(r[3]) : "r"(addr));
}
// fp16 in, fp16 accumulate: d = {c0c1, c2c3} packed half2
__device__ __forceinline__ void mma16816h(uint32_t* d, const uint32_t* a,
                                          uint32_t b0, uint32_t b1) {
    asm volatile(
        "mma.sync.aligned.m16n8k16.row.col.f16.f16.f16.f16 "
        "{%0,%1}, {%2,%3,%4,%5}, {%6,%7}, {%0,%1};"
        : "+r"(d[0]), "+r"(d[1])
        : "r"(a[0]), "r"(a[1]), "r"(a[2]), "r"(a[3]), "r"(b0), "r"(b1));
}

// ---------------- packed f32x2 fast-exp ----------------
__device__ __forceinline__ uint64_t pack2(float x) {
    uint64_t r;
    asm("mov.b64 %0, {%1, %1};" : "=l"(r) : "f"(x));
    return r;
}
// e = exp(x * INV_TAU) for a pair of raw accumulator values.
__device__ __forceinline__ void fexp2(float x0, float x1, float& e0, float& e1) {
    const uint64_t cK    = pack2(14.426950408889634f);  // INV_TAU * log2(e)
    const uint64_t cMag  = pack2(12582912.0f);          // 1.5 * 2^23
    const uint64_t cNeg1 = pack2(-1.0f);
    const uint64_t c5 = pack2(1.3333558e-3f);
    const uint64_t c4 = pack2(9.6181291e-3f);
    const uint64_t c3 = pack2(5.5504109e-2f);
    const uint64_t c2 = pack2(2.4022650e-1f);
    const uint64_t c1 = pack2(6.9314718e-1f);
    const uint64_t cOne = pack2(1.0f);

    uint64_t x2, y2, t2, u2, f2, p2;
    asm("mov.b64 %0, {%1, %2};" : "=l"(x2) : "f"(x0), "f"(x1));
    asm("mul.rn.f32x2 %0, %1, %2;" : "=l"(y2) : "l"(x2), "l"(cK));
    asm("add.rn.f32x2 %0, %1, %2;" : "=l"(t2) : "l"(y2), "l"(cMag));
    asm("fma.rn.f32x2 %0, %1, %2, %3;" : "=l"(u2) : "l"(cMag), "l"(cNeg1), "l"(t2)); // t - MAGIC
    asm("fma.rn.f32x2 %0, %1, %2, %3;" : "=l"(f2) : "l"(u2), "l"(cNeg1), "l"(y2));   // y - (t-MAGIC)
    p2 = c5;
    asm("fma.rn.f32x2 %0, %1, %2, %3;" : "=l"(p2) : "l"(p2), "l"(f2), "l"(c4));
    asm("fma.rn.f32x2 %0, %1, %2, %3;" : "=l"(p2) : "l"(p2), "l"(f2), "l"(c3));
    asm("fma.rn.f32x2 %0, %1, %2, %3;" : "=l"(p2) : "l"(p2), "l"(f2), "l"(c2));
    asm("fma.rn.f32x2 %0, %1, %2, %3;" : "=l"(p2) : "l"(p2), "l"(f2), "l"(c1));
    asm("fma.rn.f32x2 %0, %1, %2, %3;" : "=l"(p2) : "l"(p2), "l"(f2), "l"(cOne));

    uint32_t tl, th, pl, ph;
    asm("mov.b64 {%0, %1}, %2;" : "=r"(tl), "=r"(th) : "l"(t2));
    asm("mov.b64 {%0, %1}, %2;" : "=r"(pl), "=r"(ph) : "l"(p2));
    // (tl - 0x4B400000) << 23 == tl << 23  (low 9 bits of the bias are zero)
    e0 = __int_as_float((int)(pl + (tl << 23)));
    e1 = __int_as_float((int)(ph + (th << 23)));
}

// ---------------- kernels ----------------
// 4 float4 per thread, loads batched first (MLP=4); fp32 -> fp16
__global__ void convert_kernel(const float* __restrict__ E) {
    const int tid = threadIdx.x;
    const int zi = blockIdx.x * 256 + tid;
    if (zi < B_SIZE) { g_S[zi] = 0.f; g_P[zi] = 0.f; g_C[zi] = 0; }
    if (zi == 0) { g_pl = 0.f; g_pc = 0; g_ticket = 0; }

    const int base = blockIdx.x * 1024 + tid;
    const float4* Ep = reinterpret_cast<const float4*>(E);
    float4 v[4];
#pragma unroll
    for (int k = 0; k < 4; k++) v[k] = Ep[base + k * 256];
    __half2* hp = reinterpret_cast<__half2*>(g_Ehf);
#pragma unroll
    for (int k = 0; k < 4; k++) {
        const int idx = base + k * 256;
        hp[idx * 2 + 0] = __floats2half2_rn(v[k].x, v[k].y);
        hp[idx * 2 + 1] = __floats2half2_rn(v[k].z, v[k].w);
    }
}

__device__ __forceinline__ void load_chunk(uint32_t sb, int stage, int m0, int n0,
                                           int chunk, int tid) {
    const char* eb = reinterpret_cast<const char*>(g_Ehf);
    uint32_t sbase = sb + stage * STAGE_BYTES;
    size_t colb = (size_t)chunk * 128;
#pragma unroll
    for (int q = 0; q < 8; q++) {
        int idx = tid + q * 128;        // 0..1023
        int row = idx >> 3;             // 0..127
        int c16 = idx & 7;
        uint32_t sw = row * 128 + ((c16 * 16) ^ ((row & 7) << 4));
        size_t gA = (size_t)(m0 + row) * 2048 + colb + c16 * 16;
        size_t gB = (size_t)(n0 + row) * 2048 + colb + c16 * 16;
        cp_async16(sbase + sw, eb + gA);
        cp_async16(sbase + OFF_B + sw, eb + gB);
    }
}

__global__ void __launch_bounds__(128, 3)
sim_kernel(const long long* __restrict__ labels) {
    // l < NOFFD: strictly-upper (bi < bj); l >= NOFFD: diagonal tiles (cheap, last)
    const int l = blockIdx.x;
    int bi, bj;
    if (l < NOFFD) {
        int g = (int)(63.5f - sqrtf(fmaxf(63.5f * 63.5f - 2.0f * (float)l, 0.f)));
        if (g > 62) g = 62;
        if (g < 0) g = 0;
        while (g > 0 && 63 * g - (g * (g - 1)) / 2 > l) g--;
        while (63 * (g + 1) - ((g + 1) * g) / 2 <= l) g++;
        bi = g;
        bj = g + 1 + (l - (63 * g - (g * (g - 1)) / 2));
    } else {
        bi = bj = l - NOFFD;
    }

    extern __shared__ char smem[];
    const uint32_t sb = smem_u32(smem);
    const int tid = threadIdx.x;
    const int wid = tid >> 5, lane = tid & 31;
    const int m0 = bi * TM, n0 = bj * TN;
    const bool diagTile = (bi == bj);

    int*   lAs = reinterpret_cast<int*>(smem + SM_LA);
    int*   lBs = reinterpret_cast<int*>(smem + SM_LB);
    float* rS = reinterpret_cast<float*>(smem + SM_RS);
    float* rP = reinterpret_cast<float*>(smem + SM_RP);
    float* cS = reinterpret_cast<float*>(smem + SM_CS);
    float* cP = reinterpret_cast<float*>(smem + SM_CP);
    int*   hA = reinterpret_cast<int*>(smem + SM_HA);
    int*   hB = reinterpret_cast<int*>(smem + SM_HB);

    load_chunk(sb, 0, m0, n0, 0, tid); cp_commit();
    load_chunk(sb, 1, m0, n0, 1, tid); cp_commit();

    if (tid < 128) {
        lAs[tid] = (int)labels[m0 + tid];
        lBs[tid] = (int)labels[n0 + tid];
        rS[tid] = 0.f; rP[tid] = 0.f;
        cS[tid] = 0.f; cP[tid] = 0.f;
        hA[tid] = 0; hA[tid + 128] = 0;
        hB[tid] = 0; hB[tid + 128] = 0;
    }
    __syncthreads();
    if (tid < 128) {
        atomicAdd(&hA[lAs[tid] & 255], 1);
        atomicAdd(&hB[lBs[tid] & 255], 1);
    }

    // 4 warps, 2x2; warp tile = 64 rows x 64 cols
    const int wr = wid >> 1, wc = wid & 1;
    const int qr = lane >> 2, qc = lane & 3;
    const uint32_t xmask = (lane & 7) << 4;
    const uint32_t rsel = lane & 15;
    const uint32_t csel = (lane >> 4) << 4;
    uint32_t a_row[4], b_row[4];
#pragma unroll
    for (int g = 0; g < 4; g++) {
        a_row[g] = (wr * 64 + g * 16 + rsel) * 128;
        b_row[g] = (wc * 64 + g * 16 + rsel) * 128 + OFF_B;
    }

    // fp16x2 accumulators: acc[i][j][h] packs cols (cc=0,1) of row-group h
    uint32_t acc[4][8][2];
#pragma unroll
    for (int i = 0; i < 4; i++)
#pragma unroll
        for (int j = 0; j < 8; j++) { acc[i][j][0] = 0u; acc[i][j][1] = 0u; }

    uint32_t a[2][4][4], b[2][4][4];   // register double buffer

    for (int t = 0; t < NCHUNK; t++) {
        if (t < NCHUNK - 1) asm volatile("cp.async.wait_group 1;" ::: "memory");
        else                asm volatile("cp.async.wait_group 0;" ::: "memory");
        __syncthreads();

        const uint32_t stg = sb + (t & 1) * STAGE_BYTES;

        // preload ks=0 fragments
        {
            const uint32_t co = csel ^ xmask;
#pragma unroll
            for (int g = 0; g < 4; g++) ldsm4(stg + a_row[g] + co, a[0][g]);
#pragma unroll
            for (int g = 0; g < 4; g++) ldsm4(stg + b_row[g] + co, b[0][g]);
        }

#pragma unroll
        for (int ks = 0; ks < 4; ks++) {
            const int cur = ks & 1, nxt = cur ^ 1;
            if (ks < 3) {
                const uint32_t co = ((ks + 1) * 32 + csel) ^ xmask;
#pragma unroll
                for (int g = 0; g < 4; g++) ldsm4(stg + a_row[g] + co, a[nxt][g]);
#pragma unroll
                for (int g = 0; g < 4; g++) ldsm4(stg + b_row[g] + co, b[nxt][g]);
            }
#pragma unroll
            for (int i = 0; i < 4; i++)
#pragma unroll
                for (int j = 0; j < 8; j++)
                    mma16816h(acc[i][j], a[cur][i],
                              b[cur][j >> 1][j & 1], b[cur][j >> 1][(j & 1) + 2]);
        }

        // refill the just-consumed stage with chunk t+2
        if (t + 2 < NCHUNK) {
            __syncthreads();
            load_chunk(sb, t & 1, m0, n0, t + 2, tid);
            cp_commit();
        }
    }

    // ---- fused epilogue (f32x2 exp; counts via histogram; raw-acc pos sums) ----
    int rowl[8], la[8];
#pragma unroll
    for (int i = 0; i < 4; i++)
#pragma unroll
        for (int h = 0; h < 2; h++) {
            int ri = i * 2 + h;
            rowl[ri] = wr * 64 + i * 16 + h * 8 + qr;
            la[ri] = lAs[rowl[ri]];
        }
    float rs[8], rp[8];
#pragma unroll
    for (int ri = 0; ri < 8; ri++) { rs[ri] = 0.f; rp[ri] = 0.f; }

    if (!diagTile) {
        // common path: no diag predicate anywhere
#pragma unroll
        for (int j = 0; j < 8; j++) {
            const int lc0 = wc * 64 + j * 8 + qc * 2;
            const int lc1 = lc0 + 1;
            const int lb0 = lBs[lc0], lb1 = lBs[lc1];
            float cs0 = 0.f, cp0 = 0.f, cs1 = 0.f, cp1 = 0.f;
#pragma unroll
            for (int i = 0; i < 4; i++)
#pragma unroll
                for (int h = 0; h < 2; h++) {
                    const int ri = i * 2 + h;
                    const float2 xv = __half22float2(
                        *reinterpret_cast<const __half2*>(&acc[i][j][h]));
                    const float x0 = xv.x, x1 = xv.y;
                    float e0, e1;
                    fexp2(x0, x1, e0, e1);
                    rs[ri] += e0; cs0 += e0;
                    rs[ri] += e1; cs1 += e1;
                    const float m0v = (lb0 == la[ri]) ? x0 : 0.f;
                    const float m1v = (lb1 == la[ri]) ? x1 : 0.f;
                    rp[ri] += m0v; cp0 += m0v;
                    rp[ri] += m1v; cp1 += m1v;
                }
            // reduce across qr lanes (stride 4): 8 partials -> 1
#pragma unroll
            for (int o = 4; o <= 16; o <<= 1) {
                cs0 += __shfl_xor_sync(0xFFFFFFFFu, cs0, o);
                cp0 += __shfl_xor_sync(0xFFFFFFFFu, cp0, o);
                cs1 += __shfl_xor_sync(0xFFFFFFFFu, cs1, o);
                cp1 += __shfl_xor_sync(0xFFFFFFFFu, cp1, o);
            }
            if (qr == 0) {
                atomicAdd(&cS[lc0], cs0);
                atomicAdd(&cP[lc0], cp0);
                atomicAdd(&cS[lc1], cs1);
                atomicAdd(&cP[lc1], cp1);
            }
        }
    } else {
        // diagonal tile: predicate out self-pairs; no col stats
#pragma unroll
        for (int j = 0; j < 8; j++) {
            const int lc0 = wc * 64 + j * 8 + qc * 2;
            const int lc1 = lc0 + 1;
            const int lb0 = lBs[lc0], lb1 = lBs[lc1];
#pragma unroll
            for (int i = 0; i < 4; i++)
#pragma unroll
                for (int h = 0; h < 2; h++) {
                    const int ri = i * 2 + h;
                    const float2 xv = __half22float2(
                        *reinterpret_cast<const __half2*>(&acc[i][j][h]));
                    const float x0 = xv.x, x1 = xv.y;
                    float e0, e1;
                    fexp2(x0, x1, e0, e1);
                    if (rowl[ri] != lc0) {
                        rs[ri] += e0;
                        if (lb0 == la[ri]) rp[ri] += x0;
                    }
                    if (rowl[ri] != lc1) {
                        rs[ri] += e1;
                        if (lb1 == la[ri]) rp[ri] += x1;
                    }
                }
        }
    }
    // reduce row stats across qc lanes (stride 1): 4 partials -> 1
#pragma unroll
    for (int ri = 0; ri < 8; ri++) {
#pragma unroll
        for (int o = 1; o <= 2; o <<= 1) {
            rs[ri] += __shfl_xor_sync(0xFFFFFFFFu, rs[ri], o);
            rp[ri] += __shfl_xor_sync(0xFFFFFFFFu, rp[ri], o);
        }
        if (qc == 0) {
            atomicAdd(&rS[rowl[ri]], rs[ri]);
            atomicAdd(&rP[rowl[ri]], rp[ri]);
        }
    }
    __syncthreads();

    if (tid < 128) {
        atomicAdd(&g_S[m0 + tid], rS[tid]);
        atomicAdd(&g_P[m0 + tid], rP[tid] * INV_TAU);
        atomicAdd(&g_C[m0 + tid], hB[lAs[tid] & 255] - (diagTile ? 1 : 0));
        if (!diagTile) {
            atomicAdd(&g_S[n0 + tid], cS[tid]);
            atomicAdd(&g_P[n0 + tid], cP[tid] * INV_TAU);
            atomicAdd(&g_C[n0 + tid], hA[lBs[tid] & 255]);
        }
    }
}

// 64 blocks x 128 threads; last block finalizes via ticket.
__global__ void reduce_kernel(float* __restrict__ out) {
    const int tid = threadIdx.x;
    const int r = blockIdx.x * 128 + tid;
    float loss = 0.f; int cnt = 0;
    const int c = g_C[r];
    if (c > 0) { loss = logf(g_S[r]) - g_P[r] / (float)c; cnt = 1; }
#pragma unroll
    for (int o = 16; o > 0; o >>= 1) {
        loss += __shfl_down_sync(0xFFFFFFFFu, loss, o);
        cnt  += __shfl_down_sync(0xFFFFFFFFu, cnt, o);
    }
    __shared__ float sl[4];
    __shared__ int   sc[4];
    if ((tid & 31) == 0) { sl[tid >> 5] = loss; sc[tid >> 5] = cnt; }
    __syncthreads();
    if (tid == 0) {
        float L = sl[0] + sl[1] + sl[2] + sl[3];
        int   C = sc[0] + sc[1] + sc[2] + sc[3];
        atomicAdd(&g_pl, L);
        atomicAdd(&g_pc, C);
        __threadfence();
        int prev = atomicAdd(&g_ticket, 1);
        if (prev == 63) {
            float tl = atomicAdd(&g_pl, 0.f);
            int   tc = atomicAdd(&g_pc, 0);
            out[0] = tl / (float)(tc > 0 ? tc : 1);
        }
    }
}

// ---------------- launch ----------------
extern "C" void kernel_launch(void* const* d_in, const int* in_sizes, int n_in,
                              void* d_out, int out_size) {
    const float*     E      = (const float*)d_in[0];
    const long long* labels = (const long long*)d_in[1];
    float*           out    = (float*)d_out;

    cudaFuncSetAttribute(sim_kernel, cudaFuncAttributeMaxDynamicSharedMemorySize, SMEM_TOTAL);

    convert_kernel<<<(B_SIZE * D_SIZE / 4) / 1024, 256>>>(E);

    sim_kernel<<<NTILES, 128, SMEM_TOTAL>>>(labels);

    reduce_kernel<<<64, 128>>>(out);
}